// round 2
// baseline (speedup 1.0000x reference)
#include <cuda_runtime.h>

#define CG 16
#define HW 4096
#define NG 512            // b*g groups

// ---------------- scratch (static device allocations are allowed) ----------
__device__ float g_x3[(size_t)NG * CG * HW];   // conv3x3 output (relu'd), 134MB
__device__ float g_ah[NG * CG * 64];
__device__ float g_aw[NG * CG * 64];
__device__ float g_cs[NG * CG * 6];            // k, d, max2, max3, V2, V3

// ---------------- warp reduce helpers --------------------------------------
__device__ __forceinline__ float wsum(float v){
  #pragma unroll
  for (int o = 16; o; o >>= 1) v += __shfl_xor_sync(0xffffffffu, v, o);
  return v;
}
__device__ __forceinline__ float wmax(float v){
  #pragma unroll
  for (int o = 16; o; o >>= 1) v = fmaxf(v, __shfl_xor_sync(0xffffffffu, v, o));
  return v;
}
__device__ __forceinline__ float wmin(float v){
  #pragma unroll
  for (int o = 16; o; o >>= 1) v = fminf(v, __shfl_xor_sync(0xffffffffu, v, o));
  return v;
}

// ---------------- dynamic smem layout for KA (floats) -----------------------
#define TILE_RP 68                 // row pitch (1 zero col + 64 data + 1 zero + 2 pad)
#define TILE_CP (18 * TILE_RP)     // channel pitch (18 rows incl. vertical halo)
#define SM_TILE 0                  // 16*18*68 = 19584 floats
#define SM_AH   19584              // 1024
#define SM_AW   20608              // 1024
#define SM_W3   21632              // 2304
#define SM_TOTF 23936              // total floats = 95744 bytes

__global__ void __launch_bounds__(512, 2) ka_kernel(
    const float* __restrict__ x,
    const float* __restrict__ w1, const float* __restrict__ b1,
    const float* __restrict__ wh, const float* __restrict__ bh,
    const float* __restrict__ ww, const float* __restrict__ bw,
    const float* __restrict__ w3, const float* __restrict__ b3,
    const float* __restrict__ gnw, const float* __restrict__ gnb)
{
  extern __shared__ float sm[];
  float* tile = sm + SM_TILE;
  float* s_ah = sm + SM_AH;
  float* s_aw = sm + SM_AW;
  float* s_w3 = sm + SM_W3;
  // phase-1 regions live inside the tile region (freed before conv)
  float* s_xh = sm;            // [16][64]
  float* s_xw = sm + 1024;     // [16][64]
  float* s_y  = sm + 2048;     // [16][128]
  float* s_W  = sm + 4096;     // W1(256) Wh(256) Ww(256)
  float* s_bb = sm + 4864;     // b1(16) bh(16) bw(16)

  __shared__ float s_b3[16];
  __shared__ float schmax3[16], schsum3[16];
  __shared__ float schsum1[16], schmax1[16], schmin1[16];
  __shared__ float s_rg[16], s_rq[16];
  __shared__ float s_mu, s_rs;

  const int t = threadIdx.x, warp = t >> 5, lane = t & 31;
  const int g = blockIdx.x;
  const float* xg = x + (size_t)g * CG * HW;

  // ---- load small weights / init reductions ----
  if (t < 256) { s_W[t] = w1[t]; s_W[256 + t] = wh[t]; s_W[512 + t] = ww[t]; }
  if (t < 16) {
    s_bb[t] = b1[t]; s_bb[16 + t] = bh[t]; s_bb[32 + t] = bw[t];
    s_b3[t] = b3[t]; schmax3[t] = 0.f; schsum3[t] = 0.f;
  }
  for (int i = t; i < 2304; i += 512) s_w3[i] = w3[i];

  // ---- phase 1: row/col means (warp == channel) ----
  {
    const float* xc = xg + warp * HW;
    float cs0 = 0.f, cs1 = 0.f;
    for (int i = 0; i < 64; i++) {
      float v0 = xc[i * 64 + lane];
      float v1 = xc[i * 64 + lane + 32];
      cs0 += v0; cs1 += v1;
      float rsum = wsum(v0 + v1);
      if (lane == 0) s_xh[warp * 64 + i] = rsum * (1.f / 64.f);
    }
    s_xw[warp * 64 + lane]      = cs0 * (1.f / 64.f);
    s_xw[warp * 64 + lane + 32] = cs1 * (1.f / 64.f);
  }
  __syncthreads();

  // ---- phase 1b: y = relu(W1 @ [xh;xw] + b1) ----
  if (t < 128) {
    float in[16];
    #pragma unroll
    for (int i = 0; i < 16; i++)
      in[i] = (t < 64) ? s_xh[i * 64 + t] : s_xw[i * 64 + (t - 64)];
    #pragma unroll
    for (int o = 0; o < 16; o++) {
      float acc = s_bb[o];
      #pragma unroll
      for (int i = 0; i < 16; i++) acc = fmaf(s_W[o * 16 + i], in[i], acc);
      s_y[o * 128 + t] = fmaxf(acc, 0.f);
    }
  }
  __syncthreads();
  // ---- a_h = sigmoid(Wh @ y_h + bh), a_w = sigmoid(Ww @ y_w + bw) ----
  if (t < 128) {
    const int half = t >> 6, col = t & 63;
    const float* Wm = s_W + 256 + half * 256;
    const float* bm = s_bb + 16 + half * 16;
    float in[16];
    #pragma unroll
    for (int i = 0; i < 16; i++) in[i] = s_y[i * 128 + t];
    float* dst  = half ? s_aw : s_ah;
    float* gdst = half ? (g_aw + g * 1024) : (g_ah + g * 1024);
    #pragma unroll
    for (int o = 0; o < 16; o++) {
      float acc = bm[o];
      #pragma unroll
      for (int i = 0; i < 16; i++) acc = fmaf(Wm[o * 16 + i], in[i], acc);
      float sg = 1.f / (1.f + __expf(-acc));
      dst[o * 64 + col] = sg;
      gdst[o * 64 + col] = sg;
    }
  }

  // ---- phase 2: conv3x3 + x1/x3 statistics, 4 strips of 16 rows ----
  float gs = 0.f, gsq = 0.f;
  float c1sum = 0.f, c1max = -1e30f, c1min = 1e30f;
  const int ocp = t >> 6, oc0 = ocp * 2, oc1 = oc0 + 1;
  float m30 = 0.f, m31 = 0.f, s30 = 0.f, s31 = 0.f;

  for (int r0 = 0; r0 < 64; r0 += 16) {
    __syncthreads();                       // previous tile readers done
    // load strip (rows r0-1 .. r0+16) with zero halo
    for (int idx = t; idx < 4608; idx += 512) {
      int c = idx / 288;
      int rem = idx - c * 288;
      int rr = rem >> 4, q = rem & 15;
      int gr = r0 - 1 + rr;
      float4 v = make_float4(0.f, 0.f, 0.f, 0.f);
      if ((unsigned)gr < 64u)
        v = *reinterpret_cast<const float4*>(xg + c * HW + gr * 64 + q * 4);
      float* d = tile + c * TILE_CP + rr * TILE_RP + 1 + q * 4;
      d[0] = v.x; d[1] = v.y; d[2] = v.z; d[3] = v.w;
    }
    if (t < 288) {
      int c = t / 18, rr = t - c * 18;
      float* row = tile + c * TILE_CP + rr * TILE_RP;
      row[0] = 0.f; row[65] = 0.f;
    }
    __syncthreads();

    // x1 stats (warp == channel)
    {
      const float* tc  = tile + warp * TILE_CP;
      const float* ahc = s_ah + warp * 64;
      const float* awc = s_aw + warp * 64;
      float aw0 = awc[lane], aw1 = awc[lane + 32];
      #pragma unroll 4
      for (int r = 0; r < 16; r++) {
        float a = ahc[r0 + r];
        const float* rowp = tc + (r + 1) * TILE_RP + 1;
        float v0 = rowp[lane] * a * aw0;
        float v1 = rowp[lane + 32] * a * aw1;
        gs += v0 + v1;
        gsq += v0 * v0 + v1 * v1;
        c1sum += v0 + v1;
        c1max = fmaxf(c1max, fmaxf(v0, v1));
        c1min = fminf(c1min, fminf(v0, v1));
      }
    }

    // conv: each thread computes 2 tiles of (2 outch x 8 px)
    #pragma unroll 1
    for (int it = 0; it < 2; it++) {
      int ti = (t & 63) + (it << 6);
      int rr = ti >> 3, cb = ti & 7;
      float acc0[8], acc1[8];
      #pragma unroll
      for (int p = 0; p < 8; p++) { acc0[p] = 0.f; acc1[p] = 0.f; }
      const float* tb  = tile + rr * TILE_RP + cb * 8;
      const float* wp0 = s_w3 + oc0 * 144;
      const float* wp1 = s_w3 + oc1 * 144;
      #pragma unroll 1
      for (int ci = 0; ci < 16; ci++) {
        const float* tcb = tb + ci * TILE_CP;
        const float* wa9 = wp0 + ci * 9;
        const float* wb9 = wp1 + ci * 9;
        #pragma unroll
        for (int dr = 0; dr < 3; dr++) {
          const float4 q0 = *reinterpret_cast<const float4*>(tcb + dr * TILE_RP);
          const float4 q1 = *reinterpret_cast<const float4*>(tcb + dr * TILE_RP + 4);
          const float2 q2 = *reinterpret_cast<const float2*>(tcb + dr * TILE_RP + 8);
          float xr[10] = {q0.x, q0.y, q0.z, q0.w, q1.x, q1.y, q1.z, q1.w, q2.x, q2.y};
          float wa0 = wa9[dr * 3], wa1 = wa9[dr * 3 + 1], wa2 = wa9[dr * 3 + 2];
          float wb0 = wb9[dr * 3], wb1 = wb9[dr * 3 + 1], wb2 = wb9[dr * 3 + 2];
          #pragma unroll
          for (int p = 0; p < 8; p++) {
            acc0[p] = fmaf(xr[p], wa0, fmaf(xr[p + 1], wa1, fmaf(xr[p + 2], wa2, acc0[p])));
            acc1[p] = fmaf(xr[p], wb0, fmaf(xr[p + 1], wb1, fmaf(xr[p + 2], wb2, acc1[p])));
          }
        }
      }
      int grow = r0 + rr;
      float bz0 = s_b3[oc0], bz1 = s_b3[oc1];
      #pragma unroll
      for (int p = 0; p < 8; p++) {
        float u0 = fmaxf(acc0[p] + bz0, 0.f);
        float u1 = fmaxf(acc1[p] + bz1, 0.f);
        acc0[p] = u0; acc1[p] = u1;
        m30 = fmaxf(m30, u0); m31 = fmaxf(m31, u1);
        s30 += u0; s31 += u1;
      }
      float* o0 = g_x3 + ((size_t)g * CG + oc0) * HW + grow * 64 + cb * 8;
      float* o1 = g_x3 + ((size_t)g * CG + oc1) * HW + grow * 64 + cb * 8;
      *reinterpret_cast<float4*>(o0)     = make_float4(acc0[0], acc0[1], acc0[2], acc0[3]);
      *reinterpret_cast<float4*>(o0 + 4) = make_float4(acc0[4], acc0[5], acc0[6], acc0[7]);
      *reinterpret_cast<float4*>(o1)     = make_float4(acc1[0], acc1[1], acc1[2], acc1[3]);
      *reinterpret_cast<float4*>(o1 + 4) = make_float4(acc1[4], acc1[5], acc1[6], acc1[7]);
    }
  }

  // ---- reductions ----
  gs = wsum(gs); gsq = wsum(gsq);
  c1sum = wsum(c1sum); c1max = wmax(c1max); c1min = wmin(c1min);
  if (lane == 0) {
    s_rg[warp] = gs; s_rq[warp] = gsq;
    schsum1[warp] = c1sum; schmax1[warp] = c1max; schmin1[warp] = c1min;
  }
  atomicAdd(&schsum3[oc0], s30);
  atomicAdd(&schsum3[oc1], s31);
  atomicMax(reinterpret_cast<int*>(&schmax3[oc0]), __float_as_int(m30)); // relu >= 0
  atomicMax(reinterpret_cast<int*>(&schmax3[oc1]), __float_as_int(m31));
  __syncthreads();
  if (t == 0) {
    float a = 0.f, bq = 0.f;
    #pragma unroll
    for (int i = 0; i < 16; i++) { a += s_rg[i]; bq += s_rq[i]; }
    float mu = a * (1.f / 65536.f);
    float var = bq * (1.f / 65536.f) - mu * mu;
    s_mu = mu; s_rs = rsqrtf(var + 1e-5f);
  }
  __syncthreads();
  if (t < 16) {
    int c = t;
    float k = s_rs * gnw[c];
    float d = gnb[c] - s_mu * k;
    float mx1 = (k >= 0.f) ? schmax1[c] : schmin1[c];
    float max2 = mx1 * k + d;
    float V2 = schsum1[c] * (1.f / 4096.f) * k + d;
    float V3 = schsum3[c] * (1.f / 4096.f);
    float* cs = g_cs + (g * CG + c) * 6;
    cs[0] = k; cs[1] = d; cs[2] = max2; cs[3] = schmax3[c]; cs[4] = V2; cs[5] = V3;
  }
}

// ---------------------------------------------------------------------------
__global__ void __launch_bounds__(512) kb_kernel(const float* __restrict__ x,
                                                 float* __restrict__ out)
{
  __shared__ float s_s[4096];
  __shared__ float s_ah[1024], s_aw[1024];
  __shared__ float s_k[16], s_e2[16], s_m3[16], s_w2[16], s_w3[16];
  __shared__ float s_r1[16];
  __shared__ float s_smax, s_sinv;

  const int t = threadIdx.x, warp = t >> 5, lane = t & 31;
  const int g = blockIdx.x;
  const float* xg  = x + (size_t)g * CG * HW;
  const float* x3g = g_x3 + (size_t)g * CG * HW;

  for (int i = t; i < 1024; i += 512) {
    s_ah[i] = g_ah[g * 1024 + i];
    s_aw[i] = g_aw[g * 1024 + i];
  }
  if (t < 16) {
    const float* cs = g_cs + (g * CG + t) * 6;
    s_k[t]  = cs[0];
    s_e2[t] = cs[1] - cs[2];   // d - max2
    s_m3[t] = cs[3];
    s_w3[t] = cs[4];           // V2 (divided by Z3 below)
    s_w2[t] = cs[5];           // V3 (divided by Z2 below)
  }
  __syncthreads();

  // pass 1: per-channel Z2, Z3 (warp == channel)
  {
    const int c = warp;
    float k = s_k[c], e2 = s_e2[c], m3 = s_m3[c];
    const float* xc  = xg + c * HW;
    const float* x3c = x3g + c * HW;
    const float* ahc = s_ah + c * 64;
    const float* awc = s_aw + c * 64;
    float z2 = 0.f, z3 = 0.f;
    for (int m = 0; m < 128; m++) {
      int l = m * 32 + lane;
      float x1 = xc[l] * ahc[l >> 6] * awc[l & 63];
      z2 += __expf(fmaf(x1, k, e2));
      z3 += __expf(x3c[l] - m3);
    }
    z2 = wsum(z2); z3 = wsum(z3);
    if (lane == 0) { s_w3[c] = s_w3[c] / z3; s_w2[c] = s_w2[c] / z2; }
  }
  __syncthreads();

  // pass 2: s logits
  float lmax = -1e30f;
  #pragma unroll 1
  for (int rep = 0; rep < 8; rep++) {
    int l = t + rep * 512;
    int i = l >> 6, j = l & 63;
    float acc = 0.f;
    #pragma unroll
    for (int c = 0; c < 16; c++) {
      float x1 = xg[c * HW + l] * s_ah[c * 64 + i] * s_aw[c * 64 + j];
      acc += s_w2[c] * __expf(fmaf(x1, s_k[c], s_e2[c]));
      acc += s_w3[c] * __expf(x3g[c * HW + l] - s_m3[c]);
    }
    s_s[l] = acc;
    lmax = fmaxf(lmax, acc);
  }
  lmax = wmax(lmax);
  if (lane == 0) s_r1[warp] = lmax;
  __syncthreads();
  if (t == 0) {
    float m = -1e30f;
    #pragma unroll
    for (int i = 0; i < 16; i++) m = fmaxf(m, s_r1[i]);
    s_smax = m;
  }
  __syncthreads();
  float lsum = 0.f;
  #pragma unroll 1
  for (int rep = 0; rep < 8; rep++) {
    int l = t + rep * 512;
    lsum += __expf(s_s[l] - s_smax);
  }
  lsum = wsum(lsum);
  if (lane == 0) s_r1[warp] = lsum;
  __syncthreads();
  if (t == 0) {
    float a = 0.f;
    #pragma unroll
    for (int i = 0; i < 16; i++) a += s_r1[i];
    s_sinv = 1.f / a;
  }
  __syncthreads();
  #pragma unroll 1
  for (int rep = 0; rep < 8; rep++) {
    int l = t + rep * 512;
    s_s[l] = __expf(s_s[l] - s_smax) * s_sinv;
  }
  __syncthreads();

  // pass 3: out = x * s
  float* og = out + (size_t)g * CG * HW;
  #pragma unroll 1
  for (int c = 0; c < 16; c++) {
    #pragma unroll
    for (int rep = 0; rep < 8; rep++) {
      int l = t + rep * 512;
      og[c * HW + l] = xg[c * HW + l] * s_s[l];
    }
  }
}

// ---------------------------------------------------------------------------
extern "C" void kernel_launch(void* const* d_in, const int* in_sizes, int n_in,
                              void* d_out, int out_size)
{
  const float* x   = (const float*)d_in[0];
  const float* w1  = (const float*)d_in[1];
  const float* b1  = (const float*)d_in[2];
  const float* wh  = (const float*)d_in[3];
  const float* bh  = (const float*)d_in[4];
  const float* ww  = (const float*)d_in[5];
  const float* bw  = (const float*)d_in[6];
  const float* w3  = (const float*)d_in[7];
  const float* b3  = (const float*)d_in[8];
  const float* gnw = (const float*)d_in[9];
  const float* gnb = (const float*)d_in[10];

  cudaFuncSetAttribute(ka_kernel, cudaFuncAttributeMaxDynamicSharedMemorySize,
                       SM_TOTF * (int)sizeof(float));
  ka_kernel<<<NG, 512, SM_TOTF * sizeof(float)>>>(x, w1, b1, wh, bh, ww, bw, w3, b3, gnw, gnb);
  kb_kernel<<<NG, 512>>>(x, (float*)d_out);
}